// round 14
// baseline (speedup 1.0000x reference)
#include <cuda_runtime.h>
#include <math.h>
#include <float.h>
#include <stdint.h>

// ---------------------------------------------------------------------------
// MLA prefill. B=2, S=2048, HIDDEN=2048, H=16, Q_LORA=768, KV_LORA=512,
// NOPE=128, ROPE=64, QK_HEAD=192, V_DIM=128.
// Outputs: attn_output (B,S,2048) then attn_weights (B,H,S,S), fp32.
// GEMMs via mma.sync m16n8k8 tf32.  R9 engine + PREFETCH DISTANCE 2:
// gload(kt+2) / sstore(kt+1) / compute(kt) / one barrier — hides global-load
// latency across a full K-chunk instead of exposing it every chunk.
// No cp.async / dynamic smem / tcgen05 (harness ptxas target rejects them).
// ---------------------------------------------------------------------------

#define S_LEN   2048
#define BATCH   2
#define NHEADS  16

// Scratch (device globals: no allocations allowed)
__device__ float g_qa[4096 * 768];
__device__ float g_q[(long long)4096 * 3072];
__device__ float g_kvfull[4096 * 576];
__device__ float g_kv_ext[4096 * 576];
__device__ float g_q_ext[(long long)32 * 2048 * 576];
__device__ float g_ctx[(long long)32 * 2048 * 512];
__device__ float g_out[(long long)4096 * 2048];
__device__ float g_wbT[16 * 512 * 128];            // transposed wkv_b nope slice
__device__ float g_kvT[(long long)2 * 512 * 2048]; // transposed kv latent

__device__ __forceinline__ uint32_t f2tf(float x) {
    uint32_t r;
    asm("cvt.rna.tf32.f32 %0, %1;" : "=r"(r) : "f"(x));
    return r;
}

__device__ __forceinline__ void mma_tf32(float* c, const uint32_t* a,
                                         const uint32_t* b) {
    asm volatile(
        "mma.sync.aligned.m16n8k8.row.col.f32.tf32.tf32.f32 "
        "{%0,%1,%2,%3}, {%4,%5,%6,%7}, {%8,%9}, {%0,%1,%2,%3};"
        : "+f"(c[0]), "+f"(c[1]), "+f"(c[2]), "+f"(c[3])
        : "r"(a[0]), "r"(a[1]), "r"(a[2]), "r"(a[3]), "r"(b[0]), "r"(b[1]));
}

#define SM_STRIDE 20   // 16 + 4 padding (uint32 words); row = 80B, float4-ok

// ---------------------------------------------------------------------------
// mma.sync tf32 GEMM:  C = alpha * A @ B^T
//   A (M,K) row-major, B (N,K) row-major.  CTA 128x128, warp 64x32,
//   K-chunk 16, DISTANCE-2 register prefetch (two staging sets), double
//   smem buffer, tf32 cvt at staging, ONE __syncthreads per chunk.
//   CAUSAL: skip blocks fully above diagonal.  KLIMIT: k stops at m0+128.
//   M % 128 == 0, K % 16 == 0; N boundary handled (zero-fill + guarded store).
// ---------------------------------------------------------------------------
template<bool CAUSAL, bool KLIMIT>
__global__ __launch_bounds__(256, 2) void gemm_mma(
    int M, int N, int K,
    const float* __restrict__ A, int lda, long long sAo, long long sAi,
    const float* __restrict__ B, int ldb, long long sBo, long long sBi,
    float* __restrict__ C, int ldc, long long sCo, long long sCi,
    int zdiv, float alpha)
{
    const int m0 = blockIdx.y * 128;
    const int n0 = blockIdx.x * 128;
    if (CAUSAL && n0 > m0 + 127) return;

    __shared__ uint32_t As[2][128 * SM_STRIDE];
    __shared__ uint32_t Bs[2][128 * SM_STRIDE];

    const int z = blockIdx.z;
    const int zo = z / zdiv, zi = z % zdiv;
    A += zo * sAo + (long long)zi * sAi;
    B += zo * sBo + (long long)zi * sBi;
    C += zo * sCo + (long long)zi * sCi;

    const int kend = KLIMIT ? min(K, m0 + 128) : K;
    const int nkt = kend >> 4;

    const int tid  = threadIdx.x;
    const int lane = tid & 31;
    const int wid  = tid >> 5;
    const int wm   = wid & 1;          // warp row (0..1)  -> 64 rows
    const int wn   = wid >> 1;         // warp col (0..3)  -> 32 cols
    const int lr   = lane >> 2;        // 0..7
    const int lc   = lane & 3;         // 0..3

    const int row = tid >> 2;          // 0..63
    const int q   = tid & 3;           // float4 index within 16 floats

    // Two staging register sets: set kt&1 holds chunk kt's global data.
    float4 ra[2][2], rb[2][2];
    auto gload = [&](int kt) {
        const int s  = kt & 1;
        const int k0 = kt << 4;
#pragma unroll
        for (int i = 0; i < 2; i++) {
            const int r = i * 64 + row;
            ra[s][i] = *reinterpret_cast<const float4*>(
                &A[(long long)(m0 + r) * lda + k0 + q * 4]);
            const int n = n0 + r;
            rb[s][i] = (n < N)
                ? *reinterpret_cast<const float4*>(
                      &B[(long long)n * ldb + k0 + q * 4])
                : make_float4(0.f, 0.f, 0.f, 0.f);
        }
    };
    auto sstore = [&](int kt) {
        const int s = kt & 1;          // register set == smem buffer parity
#pragma unroll
        for (int i = 0; i < 2; i++) {
            const int r = i * 64 + row;
            uint4 a = make_uint4(f2tf(ra[s][i].x), f2tf(ra[s][i].y),
                                 f2tf(ra[s][i].z), f2tf(ra[s][i].w));
            uint4 b = make_uint4(f2tf(rb[s][i].x), f2tf(rb[s][i].y),
                                 f2tf(rb[s][i].z), f2tf(rb[s][i].w));
            *reinterpret_cast<uint4*>(&As[s][r * SM_STRIDE + q * 4]) = a;
            *reinterpret_cast<uint4*>(&Bs[s][r * SM_STRIDE + q * 4]) = b;
        }
    };

    float acc[4][4][4];
#pragma unroll
    for (int i = 0; i < 4; i++)
#pragma unroll
        for (int j = 0; j < 4; j++)
#pragma unroll
            for (int r = 0; r < 4; r++) acc[i][j][r] = 0.f;

    // Prologue: chunk 0 staged to smem; chunk 1 in flight in registers.
    gload(0);
    sstore(0);
    if (1 < nkt) gload(1);
    __syncthreads();

    for (int kt = 0; kt < nkt; kt++) {
        if (kt + 2 < nkt) gload(kt + 2);   // issue earliest: full-chunk slack
        if (kt + 1 < nkt) sstore(kt + 1);  // its loads are ~1 chunk old

        const uint32_t* as = As[kt & 1];
        const uint32_t* bs = Bs[kt & 1];
#pragma unroll
        for (int kk = 0; kk < 16; kk += 8) {
            uint32_t bf[4][2];
#pragma unroll
            for (int nf = 0; nf < 4; nf++) {
                const int n = wn * 32 + nf * 8 + lr;
                bf[nf][0] = bs[n * SM_STRIDE + kk + lc];
                bf[nf][1] = bs[n * SM_STRIDE + kk + lc + 4];
            }
#pragma unroll
            for (int mf = 0; mf < 4; mf++) {
                const int r = wm * 64 + mf * 16 + lr;
                uint32_t af[4];
                af[0] = as[r * SM_STRIDE + kk + lc];
                af[1] = as[(r + 8) * SM_STRIDE + kk + lc];
                af[2] = as[r * SM_STRIDE + kk + lc + 4];
                af[3] = as[(r + 8) * SM_STRIDE + kk + lc + 4];
#pragma unroll
                for (int nf = 0; nf < 4; nf++)
                    mma_tf32(acc[mf][nf], af, bf[nf]);
            }
        }
        __syncthreads();
    }

    // Epilogue: direct global stores (float2 pairs), alpha applied.
#pragma unroll
    for (int mf = 0; mf < 4; mf++) {
        const int r = m0 + wm * 64 + mf * 16 + lr;
#pragma unroll
        for (int nf = 0; nf < 4; nf++) {
            const int cn = n0 + wn * 32 + nf * 8 + 2 * lc;
            if (cn < N) {
                float2 v0 = make_float2(alpha * acc[mf][nf][0],
                                        alpha * acc[mf][nf][1]);
                float2 v1 = make_float2(alpha * acc[mf][nf][2],
                                        alpha * acc[mf][nf][3]);
                *reinterpret_cast<float2*>(C + (long long)r * ldc + cn) = v0;
                *reinterpret_cast<float2*>(C + (long long)(r + 8) * ldc + cn) = v1;
            }
        }
    }
}

// ---------------------------------------------------------------------------
// RMSNorm
// ---------------------------------------------------------------------------
__global__ __launch_bounds__(256) void rmsnorm_k(
    const float* __restrict__ x, int ldx, const float* __restrict__ w,
    float* __restrict__ y, int ldy, int dim)
{
    const long long row = blockIdx.x;
    x += row * ldx; y += row * ldy;
    float s = 0.f;
    for (int i = threadIdx.x; i < dim; i += 256) { float v = x[i]; s += v * v; }
    __shared__ float red[8];
    for (int o = 16; o; o >>= 1) s += __shfl_xor_sync(0xffffffffu, s, o);
    if ((threadIdx.x & 31) == 0) red[threadIdx.x >> 5] = s;
    __syncthreads();
    if (threadIdx.x < 8) {
        float v = red[threadIdx.x];
        for (int o = 4; o; o >>= 1) v += __shfl_xor_sync(0xffu, v, o);
        if (threadIdx.x == 0) red[0] = v;
    }
    __syncthreads();
    const float r = rsqrtf(red[0] / (float)dim + 1e-6f);
    for (int i = threadIdx.x; i < dim; i += 256) y[i] = x[i] * r * w[i];
}

// ---------------------------------------------------------------------------
// RoPE
// ---------------------------------------------------------------------------
__global__ void rope_q_k(const float* __restrict__ q,
                         const float* __restrict__ cosb,
                         const float* __restrict__ sinb,
                         float* __restrict__ q_ext)
{
    const int bs = blockIdx.x, h = blockIdx.y, i = threadIdx.x;
    const int b = bs >> 11, s = bs & 2047;
    const float* x = q + (long long)bs * 3072 + h * 192 + 128;
    const float c  = cosb[(long long)bs * 64 + i];
    const float sn = sinb[(long long)bs * 64 + i];
    const float xr = (i < 32) ? -x[i + 32] : x[i - 32];
    q_ext[((long long)(b * 16 + h) * 2048 + s) * 576 + 512 + i] = x[i] * c + xr * sn;
}

__global__ void rope_k_k(const float* __restrict__ kvfull,
                         const float* __restrict__ cosb,
                         const float* __restrict__ sinb,
                         float* __restrict__ kv_ext)
{
    const int bs = blockIdx.x, i = threadIdx.x;
    const float* x = kvfull + (long long)bs * 576 + 512;
    const float c  = cosb[(long long)bs * 64 + i];
    const float sn = sinb[(long long)bs * 64 + i];
    const float xr = (i < 32) ? -x[i + 32] : x[i - 32];
    kv_ext[(long long)bs * 576 + 512 + i] = x[i] * c + xr * sn;
}

// ---------------------------------------------------------------------------
// Transpose: out[r][c] = in[c][r]   (r < R, c < Cc), z-batched
// ---------------------------------------------------------------------------
__global__ void transpose_k(const float* __restrict__ in, int ldin, long long sInz,
                            float* __restrict__ out, int ldout, long long sOutz,
                            int R, int Cc)
{
    __shared__ float t[32][33];
    in += blockIdx.z * sInz; out += blockIdx.z * sOutz;
    const int r0 = blockIdx.y * 32, c0 = blockIdx.x * 32;
    const int tx = threadIdx.x, ty = threadIdx.y;
#pragma unroll
    for (int i = 0; i < 32; i += 8) {
        const int c = c0 + ty + i, r = r0 + tx;
        if (c < Cc && r < R) t[ty + i][tx] = in[(long long)c * ldin + r];
    }
    __syncthreads();
#pragma unroll
    for (int i = 0; i < 32; i += 8) {
        const int r = r0 + ty + i, c = c0 + tx;
        if (r < R && c < Cc) out[(long long)r * ldout + c] = t[tx][ty + i];
    }
}

// ---------------------------------------------------------------------------
// Causal in-place softmax
// ---------------------------------------------------------------------------
__global__ __launch_bounds__(256) void softmax_k(float* __restrict__ P)
{
    const long long row = blockIdx.x;
    const int s = (int)(row & (S_LEN - 1));
    float* p = P + row * S_LEN;
    const int tid = threadIdx.x;

    float v[8];
    float mx = -FLT_MAX;
#pragma unroll
    for (int i = 0; i < 8; i++) {
        const int t = tid + i * 256;
        v[i] = (t <= s) ? p[t] : -FLT_MAX;
        mx = fmaxf(mx, v[i]);
    }
    __shared__ float red[8];
    for (int o = 16; o; o >>= 1) mx = fmaxf(mx, __shfl_xor_sync(0xffffffffu, mx, o));
    if ((tid & 31) == 0) red[tid >> 5] = mx;
    __syncthreads();
    if (tid < 8) {
        float m2 = red[tid];
        for (int o = 4; o; o >>= 1) m2 = fmaxf(m2, __shfl_xor_sync(0xffu, m2, o));
        if (tid == 0) red[0] = m2;
    }
    __syncthreads();
    mx = red[0];
    __syncthreads();

    float sum = 0.f;
#pragma unroll
    for (int i = 0; i < 8; i++) {
        const int t = tid + i * 256;
        v[i] = (t <= s) ? __expf(v[i] - mx) : 0.f;
        sum += v[i];
    }
    for (int o = 16; o; o >>= 1) sum += __shfl_xor_sync(0xffffffffu, sum, o);
    if ((tid & 31) == 0) red[tid >> 5] = sum;
    __syncthreads();
    if (tid < 8) {
        float s2 = red[tid];
        for (int o = 4; o; o >>= 1) s2 += __shfl_xor_sync(0xffu, s2, o);
        if (tid == 0) red[0] = s2;
    }
    __syncthreads();
    const float inv = 1.f / red[0];
#pragma unroll
    for (int i = 0; i < 8; i++) p[tid + i * 256] = v[i] * inv;
}

// ---------------------------------------------------------------------------
extern "C" void kernel_launch(void* const* d_in, const int* in_sizes, int n_in,
                              void* d_out, int out_size)
{
    const float* hs    = (const float*)d_in[0];
    const float* cosb  = (const float*)d_in[1];
    const float* sinb  = (const float*)d_in[2];
    const float* wq_a  = (const float*)d_in[4];
    const float* qnw   = (const float*)d_in[5];
    const float* wq_b  = (const float*)d_in[6];
    const float* wkv_a = (const float*)d_in[7];
    const float* kvnw  = (const float*)d_in[8];
    const float* wkv_b = (const float*)d_in[9];
    const float* wo    = (const float*)d_in[10];

    float* outp = (float*)d_out;
    float* attn = outp + (long long)BATCH * S_LEN * 2048;

    float *qa, *q, *kvf, *kve, *qe, *ctx, *obuf, *wbT, *kvT;
    cudaGetSymbolAddress((void**)&qa,   g_qa);
    cudaGetSymbolAddress((void**)&q,    g_q);
    cudaGetSymbolAddress((void**)&kvf,  g_kvfull);
    cudaGetSymbolAddress((void**)&kve,  g_kv_ext);
    cudaGetSymbolAddress((void**)&qe,   g_q_ext);
    cudaGetSymbolAddress((void**)&ctx,  g_ctx);
    cudaGetSymbolAddress((void**)&obuf, g_out);
    cudaGetSymbolAddress((void**)&wbT,  g_wbT);
    cudaGetSymbolAddress((void**)&kvT,  g_kvT);

    const float scaling = 1.f / sqrtf(192.f);
    const long long SS  = (long long)S_LEN * S_LEN;

    // 1. qa = hs @ wq_a^T               (4096 x 768, K=2048)
    gemm_mma<false, false><<<dim3(6, 32, 1), 256>>>(
        4096, 768, 2048, hs, 2048, 0, 0, wq_a, 2048, 0, 0,
        qa, 768, 0, 0, 1, 1.f);
    // 2. rmsnorm(qa)
    rmsnorm_k<<<4096, 256>>>(qa, 768, qnw, qa, 768, 768);
    // 3. q = qa @ wq_b^T                (4096 x 3072, K=768)
    gemm_mma<false, false><<<dim3(24, 32, 1), 256>>>(
        4096, 3072, 768, qa, 768, 0, 0, wq_b, 768, 0, 0,
        q, 3072, 0, 0, 1, 1.f);
    // 4. kvf = hs @ wkv_a^T             (4096 x 576, K=2048)
    gemm_mma<false, false><<<dim3(5, 32, 1), 256>>>(
        4096, 576, 2048, hs, 2048, 0, 0, wkv_a, 2048, 0, 0,
        kvf, 576, 0, 0, 1, 1.f);
    // 5-7. rmsnorm + rope
    rmsnorm_k<<<4096, 256>>>(kvf, 576, kvnw, kve, 576, 512);
    rope_k_k<<<4096, 64>>>(kvf, cosb, sinb, kve);
    rope_q_k<<<dim3(4096, 16), 64>>>(q, cosb, sinb, qe);
    // 7b. wbT[h] (512x128) = wkv_b_h[:128,:]^T
    transpose_k<<<dim3(4, 16, 16), dim3(32, 8)>>>(
        wkv_b, 512, (long long)256 * 512, wbT, 128, (long long)512 * 128,
        512, 128);
    // 8. q_ext[:, :512] = q_nope @ wbT^T  (per (b,h): 2048x512, K=128)
    gemm_mma<false, false><<<dim3(4, 16, 32), 256>>>(
        2048, 512, 128,
        q, 3072, (long long)2048 * 3072, 192,
        wbT, 128, 0, (long long)512 * 128,
        qe, 576, (long long)16 * 2048 * 576, (long long)2048 * 576,
        16, 1.f);
    // 9. scores = scaling * q_ext @ kv_ext^T (causal) -> d_out attn region
    gemm_mma<true, false><<<dim3(16, 16, 32), 256>>>(
        2048, 2048, 576,
        qe, 576, (long long)16 * 2048 * 576, (long long)2048 * 576,
        kve, 576, (long long)2048 * 576, 0,
        attn, 2048, 16 * SS, SS,
        16, scaling);
    // 10. causal softmax (in place, writes zeros above diagonal)
    softmax_k<<<BATCH * NHEADS * S_LEN, 256>>>(attn);
    // 10b. kvT[b] (512x2048) = kv_lat^T
    transpose_k<<<dim3(64, 16, 2), dim3(32, 8)>>>(
        kve, 576, (long long)2048 * 576, kvT, 2048, (long long)512 * 2048,
        512, 2048);
    // 11. ctx = P @ kvT^T  (K-limit)    (2048x512, K=2048)
    gemm_mma<false, true><<<dim3(4, 16, 32), 256>>>(
        2048, 512, 2048,
        attn, 2048, 16 * SS, SS,
        kvT, 2048, (long long)512 * 2048, 0,
        ctx, 512, (long long)16 * 2048 * 512, (long long)2048 * 512,
        16, 1.f);
    // 12. out = ctx @ wkv_b_h[:,128:]^T (per (b,h): 2048x128, K=512)
    gemm_mma<false, false><<<dim3(1, 16, 32), 256>>>(
        2048, 128, 512,
        ctx, 512, (long long)16 * 2048 * 512, (long long)2048 * 512,
        wkv_b + 128 * 512, 512, 0, (long long)256 * 512,
        obuf, 2048, (long long)2048 * 2048, 128,
        16, 1.f);
    // 13. attn_output = out @ wo^T      (4096 x 2048, K=2048)
    gemm_mma<false, false><<<dim3(16, 32, 1), 256>>>(
        4096, 2048, 2048, obuf, 2048, 0, 0, wo, 2048, 0, 0,
        outp, 2048, 0, 0, 1, 1.f);
}

// round 15
// speedup vs baseline: 2.2023x; 2.2023x over previous
#include <cuda_runtime.h>
#include <math.h>
#include <float.h>
#include <stdint.h>

// ---------------------------------------------------------------------------
// MLA prefill. B=2, S=2048, HIDDEN=2048, H=16, Q_LORA=768, KV_LORA=512,
// NOPE=128, ROPE=64, QK_HEAD=192, V_DIM=128.
// Outputs: attn_output (B,S,2048) then attn_weights (B,H,S,S), fp32.
// R9 GEMM engine (proven 2397us), restructured algebra:
//   k_nope = kv_lat @ Wb_nope^T  ->  scores K = 192 (was 576)
//   vT     = Wb_v @ kv_lat^T     ->  out = P @ vT^T (kills ctx+proj GEMMs)
// No cp.async / dynamic smem / tcgen05 (harness ptxas target rejects them).
// ---------------------------------------------------------------------------

#define S_LEN   2048
#define BATCH   2
#define NHEADS  16

// Scratch (device globals: no allocations allowed)
__device__ float g_qa[4096 * 768];
__device__ float g_q[(long long)4096 * 3072];       // q proj; pe cols roped in place
__device__ float g_kvfull[4096 * 576];
__device__ float g_kv_ext[4096 * 576];              // [rmsnorm(kv_lat) | rope(k_pe)]
__device__ float g_k_ext[(long long)32 * 2048 * 192]; // per (b,h): [k_nope | k_pe]
__device__ float g_vT[(long long)32 * 128 * 2048];    // per (b,h): V^T
__device__ float g_out[(long long)4096 * 2048];

__device__ __forceinline__ uint32_t f2tf(float x) {
    uint32_t r;
    asm("cvt.rna.tf32.f32 %0, %1;" : "=r"(r) : "f"(x));
    return r;
}

__device__ __forceinline__ void mma_tf32(float* c, const uint32_t* a,
                                         const uint32_t* b) {
    asm volatile(
        "mma.sync.aligned.m16n8k8.row.col.f32.tf32.tf32.f32 "
        "{%0,%1,%2,%3}, {%4,%5,%6,%7}, {%8,%9}, {%0,%1,%2,%3};"
        : "+f"(c[0]), "+f"(c[1]), "+f"(c[2]), "+f"(c[3])
        : "r"(a[0]), "r"(a[1]), "r"(a[2]), "r"(a[3]), "r"(b[0]), "r"(b[1]));
}

#define SM_STRIDE 20   // 16 + 4 padding (uint32 words)

// ---------------------------------------------------------------------------
// R9 engine (unchanged): C = alpha * A @ B^T.  CTA 128x128, warp 64x32,
// K-chunk 16, register-prefetch double buffer, one barrier per chunk.
// CAUSAL: skip blocks fully above diagonal.  KLIMIT: k stops at m0+128.
// M % 128 == 0, K % 16 == 0; N boundary handled.
// ---------------------------------------------------------------------------
template<bool CAUSAL, bool KLIMIT>
__global__ __launch_bounds__(256, 2) void gemm_mma(
    int M, int N, int K,
    const float* __restrict__ A, int lda, long long sAo, long long sAi,
    const float* __restrict__ B, int ldb, long long sBo, long long sBi,
    float* __restrict__ C, int ldc, long long sCo, long long sCi,
    int zdiv, float alpha)
{
    const int m0 = blockIdx.y * 128;
    const int n0 = blockIdx.x * 128;
    if (CAUSAL && n0 > m0 + 127) return;

    __shared__ uint32_t As[2][128 * SM_STRIDE];
    __shared__ uint32_t Bs[2][128 * SM_STRIDE];

    const int z = blockIdx.z;
    const int zo = z / zdiv, zi = z % zdiv;
    A += zo * sAo + (long long)zi * sAi;
    B += zo * sBo + (long long)zi * sBi;
    C += zo * sCo + (long long)zi * sCi;

    const int kend = KLIMIT ? min(K, m0 + 128) : K;
    const int nkt = kend >> 4;

    const int tid  = threadIdx.x;
    const int lane = tid & 31;
    const int wid  = tid >> 5;
    const int wm   = wid & 1;
    const int wn   = wid >> 1;
    const int lr   = lane >> 2;
    const int lc   = lane & 3;

    const int row = tid >> 2;
    const int q   = tid & 3;

    float4 ra[2], rb[2];
    auto gload = [&](int kt) {
        const int k0 = kt << 4;
#pragma unroll
        for (int i = 0; i < 2; i++) {
            const int r = i * 64 + row;
            ra[i] = *reinterpret_cast<const float4*>(
                &A[(long long)(m0 + r) * lda + k0 + q * 4]);
            const int n = n0 + r;
            rb[i] = (n < N)
                ? *reinterpret_cast<const float4*>(
                      &B[(long long)n * ldb + k0 + q * 4])
                : make_float4(0.f, 0.f, 0.f, 0.f);
        }
    };
    auto sstore = [&](int s) {
#pragma unroll
        for (int i = 0; i < 2; i++) {
            const int r = i * 64 + row;
            uint4 a = make_uint4(f2tf(ra[i].x), f2tf(ra[i].y),
                                 f2tf(ra[i].z), f2tf(ra[i].w));
            uint4 b = make_uint4(f2tf(rb[i].x), f2tf(rb[i].y),
                                 f2tf(rb[i].z), f2tf(rb[i].w));
            *reinterpret_cast<uint4*>(&As[s][r * SM_STRIDE + q * 4]) = a;
            *reinterpret_cast<uint4*>(&Bs[s][r * SM_STRIDE + q * 4]) = b;
        }
    };

    float acc[4][4][4];
#pragma unroll
    for (int i = 0; i < 4; i++)
#pragma unroll
        for (int j = 0; j < 4; j++)
#pragma unroll
            for (int r = 0; r < 4; r++) acc[i][j][r] = 0.f;

    gload(0);
    sstore(0);
    __syncthreads();

    for (int kt = 0; kt < nkt; kt++) {
        if (kt + 1 < nkt) gload(kt + 1);

        const uint32_t* as = As[kt & 1];
        const uint32_t* bs = Bs[kt & 1];
#pragma unroll
        for (int kk = 0; kk < 16; kk += 8) {
            uint32_t bf[4][2];
#pragma unroll
            for (int nf = 0; nf < 4; nf++) {
                const int n = wn * 32 + nf * 8 + lr;
                bf[nf][0] = bs[n * SM_STRIDE + kk + lc];
                bf[nf][1] = bs[n * SM_STRIDE + kk + lc + 4];
            }
#pragma unroll
            for (int mf = 0; mf < 4; mf++) {
                const int r = wm * 64 + mf * 16 + lr;
                uint32_t af[4];
                af[0] = as[r * SM_STRIDE + kk + lc];
                af[1] = as[(r + 8) * SM_STRIDE + kk + lc];
                af[2] = as[r * SM_STRIDE + kk + lc + 4];
                af[3] = as[(r + 8) * SM_STRIDE + kk + lc + 4];
#pragma unroll
                for (int nf = 0; nf < 4; nf++)
                    mma_tf32(acc[mf][nf], af, bf[nf]);
            }
        }
        if (kt + 1 < nkt) sstore((kt + 1) & 1);
        __syncthreads();
    }

#pragma unroll
    for (int mf = 0; mf < 4; mf++) {
        const int r = m0 + wm * 64 + mf * 16 + lr;
#pragma unroll
        for (int nf = 0; nf < 4; nf++) {
            const int cn = n0 + wn * 32 + nf * 8 + 2 * lc;
            if (cn < N) {
                float2 v0 = make_float2(alpha * acc[mf][nf][0],
                                        alpha * acc[mf][nf][1]);
                float2 v1 = make_float2(alpha * acc[mf][nf][2],
                                        alpha * acc[mf][nf][3]);
                *reinterpret_cast<float2*>(C + (long long)r * ldc + cn) = v0;
                *reinterpret_cast<float2*>(C + (long long)(r + 8) * ldc + cn) = v1;
            }
        }
    }
}

// ---------------------------------------------------------------------------
// RMSNorm
// ---------------------------------------------------------------------------
__global__ __launch_bounds__(256) void rmsnorm_k(
    const float* __restrict__ x, int ldx, const float* __restrict__ w,
    float* __restrict__ y, int ldy, int dim)
{
    const long long row = blockIdx.x;
    x += row * ldx; y += row * ldy;
    float s = 0.f;
    for (int i = threadIdx.x; i < dim; i += 256) { float v = x[i]; s += v * v; }
    __shared__ float red[8];
    for (int o = 16; o; o >>= 1) s += __shfl_xor_sync(0xffffffffu, s, o);
    if ((threadIdx.x & 31) == 0) red[threadIdx.x >> 5] = s;
    __syncthreads();
    if (threadIdx.x < 8) {
        float v = red[threadIdx.x];
        for (int o = 4; o; o >>= 1) v += __shfl_xor_sync(0xffu, v, o);
        if (threadIdx.x == 0) red[0] = v;
    }
    __syncthreads();
    const float r = rsqrtf(red[0] / (float)dim + 1e-6f);
    for (int i = threadIdx.x; i < dim; i += 256) y[i] = x[i] * r * w[i];
}

// ---------------------------------------------------------------------------
// In-place RoPE on q's pe columns.  32 threads per (bs,h): thread i handles
// the pair (i, i+32).  out[i]=x[i]*c[i]-x[i+32]*s[i]; out[i+32]=x[i+32]*c[i+32]
// +x[i]*s[i+32]  (rotate_half form).
// ---------------------------------------------------------------------------
__global__ void rope_q_inplace(float* __restrict__ q,
                               const float* __restrict__ cosb,
                               const float* __restrict__ sinb)
{
    const int bs = blockIdx.x, h = blockIdx.y, i = threadIdx.x;  // i: 0..31
    float* x = q + (long long)bs * 3072 + h * 192 + 128;
    const float xi = x[i], xj = x[i + 32];
    const float c0 = cosb[(long long)bs * 64 + i];
    const float s0 = sinb[(long long)bs * 64 + i];
    const float c1 = cosb[(long long)bs * 64 + i + 32];
    const float s1 = sinb[(long long)bs * 64 + i + 32];
    x[i]      = xi * c0 - xj * s0;
    x[i + 32] = xj * c1 + xi * s1;
}

// RoPE k_pe into kv_ext[512:576]
__global__ void rope_k_k(const float* __restrict__ kvfull,
                         const float* __restrict__ cosb,
                         const float* __restrict__ sinb,
                         float* __restrict__ kv_ext)
{
    const int bs = blockIdx.x, i = threadIdx.x;
    const float* x = kvfull + (long long)bs * 576 + 512;
    const float c  = cosb[(long long)bs * 64 + i];
    const float sn = sinb[(long long)bs * 64 + i];
    const float xr = (i < 32) ? -x[i + 32] : x[i - 32];
    kv_ext[(long long)bs * 576 + 512 + i] = x[i] * c + xr * sn;
}

// Broadcast roped k_pe into k_ext[.., 128:192] for every head.
__global__ void kpe_bcast(const float* __restrict__ kv_ext,
                          float* __restrict__ k_ext)
{
    const int bs = blockIdx.x, h = blockIdx.y, i = threadIdx.x;  // i: 0..63
    const int b = bs >> 11, s = bs & 2047;
    k_ext[((long long)(b * 16 + h) * 2048 + s) * 192 + 128 + i] =
        kv_ext[(long long)bs * 576 + 512 + i];
}

// ---------------------------------------------------------------------------
// Causal in-place softmax
// ---------------------------------------------------------------------------
__global__ __launch_bounds__(256) void softmax_k(float* __restrict__ P)
{
    const long long row = blockIdx.x;
    const int s = (int)(row & (S_LEN - 1));
    float* p = P + row * S_LEN;
    const int tid = threadIdx.x;

    float v[8];
    float mx = -FLT_MAX;
#pragma unroll
    for (int i = 0; i < 8; i++) {
        const int t = tid + i * 256;
        v[i] = (t <= s) ? p[t] : -FLT_MAX;
        mx = fmaxf(mx, v[i]);
    }
    __shared__ float red[8];
    for (int o = 16; o; o >>= 1) mx = fmaxf(mx, __shfl_xor_sync(0xffffffffu, mx, o));
    if ((tid & 31) == 0) red[tid >> 5] = mx;
    __syncthreads();
    if (tid < 8) {
        float m2 = red[tid];
        for (int o = 4; o; o >>= 1) m2 = fmaxf(m2, __shfl_xor_sync(0xffu, m2, o));
        if (tid == 0) red[0] = m2;
    }
    __syncthreads();
    mx = red[0];
    __syncthreads();

    float sum = 0.f;
#pragma unroll
    for (int i = 0; i < 8; i++) {
        const int t = tid + i * 256;
        v[i] = (t <= s) ? __expf(v[i] - mx) : 0.f;
        sum += v[i];
    }
    for (int o = 16; o; o >>= 1) sum += __shfl_xor_sync(0xffffffffu, sum, o);
    if ((tid & 31) == 0) red[tid >> 5] = sum;
    __syncthreads();
    if (tid < 8) {
        float s2 = red[tid];
        for (int o = 4; o; o >>= 1) s2 += __shfl_xor_sync(0xffu, s2, o);
        if (tid == 0) red[0] = s2;
    }
    __syncthreads();
    const float inv = 1.f / red[0];
#pragma unroll
    for (int i = 0; i < 8; i++) p[tid + i * 256] = v[i] * inv;
}

// ---------------------------------------------------------------------------
extern "C" void kernel_launch(void* const* d_in, const int* in_sizes, int n_in,
                              void* d_out, int out_size)
{
    const float* hs    = (const float*)d_in[0];
    const float* cosb  = (const float*)d_in[1];
    const float* sinb  = (const float*)d_in[2];
    const float* wq_a  = (const float*)d_in[4];
    const float* qnw   = (const float*)d_in[5];
    const float* wq_b  = (const float*)d_in[6];
    const float* wkv_a = (const float*)d_in[7];
    const float* kvnw  = (const float*)d_in[8];
    const float* wkv_b = (const float*)d_in[9];
    const float* wo    = (const float*)d_in[10];

    float* outp = (float*)d_out;
    float* attn = outp + (long long)BATCH * S_LEN * 2048;

    float *qa, *q, *kvf, *kve, *ke, *vT, *obuf;
    cudaGetSymbolAddress((void**)&qa,   g_qa);
    cudaGetSymbolAddress((void**)&q,    g_q);
    cudaGetSymbolAddress((void**)&kvf,  g_kvfull);
    cudaGetSymbolAddress((void**)&kve,  g_kv_ext);
    cudaGetSymbolAddress((void**)&ke,   g_k_ext);
    cudaGetSymbolAddress((void**)&vT,   g_vT);
    cudaGetSymbolAddress((void**)&obuf, g_out);

    const float scaling = 1.f / sqrtf(192.f);
    const long long SS  = (long long)S_LEN * S_LEN;

    // 1. qa = hs @ wq_a^T               (4096 x 768, K=2048)
    gemm_mma<false, false><<<dim3(6, 32, 1), 256>>>(
        4096, 768, 2048, hs, 2048, 0, 0, wq_a, 2048, 0, 0,
        qa, 768, 0, 0, 1, 1.f);
    // 2. rmsnorm(qa)
    rmsnorm_k<<<4096, 256>>>(qa, 768, qnw, qa, 768, 768);
    // 3. q = qa @ wq_b^T                (4096 x 3072, K=768)
    gemm_mma<false, false><<<dim3(24, 32, 1), 256>>>(
        4096, 3072, 768, qa, 768, 0, 0, wq_b, 768, 0, 0,
        q, 3072, 0, 0, 1, 1.f);
    // 4. kvf = hs @ wkv_a^T             (4096 x 576, K=2048)
    gemm_mma<false, false><<<dim3(5, 32, 1), 256>>>(
        4096, 576, 2048, hs, 2048, 0, 0, wkv_a, 2048, 0, 0,
        kvf, 576, 0, 0, 1, 1.f);
    // 5-7. rmsnorm + rope (k into kve, q in place)
    rmsnorm_k<<<4096, 256>>>(kvf, 576, kvnw, kve, 576, 512);
    rope_k_k<<<4096, 64>>>(kvf, cosb, sinb, kve);
    rope_q_inplace<<<dim3(4096, 16), 32>>>(q, cosb, sinb);
    // 8a. k_ext[:, :128] = kv_lat @ Wb_nope_h^T  (per (b,h): 2048x128, K=512)
    gemm_mma<false, false><<<dim3(1, 16, 32), 256>>>(
        2048, 128, 512,
        kve, 576, (long long)2048 * 576, 0,
        wkv_b, 512, 0, (long long)256 * 512,
        ke, 192, (long long)16 * 2048 * 192, (long long)2048 * 192,
        16, 1.f);
    // 8b. k_ext[:, 128:192] = broadcast roped k_pe
    kpe_bcast<<<dim3(4096, 16), 64>>>(kve, ke);
    // 8c. vT[b,h] (128x2048) = Wb_v_h @ kv_lat^T  (M=128, N=2048, K=512)
    gemm_mma<false, false><<<dim3(16, 1, 32), 256>>>(
        128, 2048, 512,
        wkv_b + 128 * 512, 512, 0, (long long)256 * 512,
        kve, 576, (long long)2048 * 576, 0,
        vT, 2048, (long long)16 * 128 * 2048, (long long)128 * 2048,
        16, 1.f);
    // 9. scores = scaling * q[:, h*192:+192] @ k_ext^T (causal, K=192)
    gemm_mma<true, false><<<dim3(16, 16, 32), 256>>>(
        2048, 2048, 192,
        q, 3072, (long long)2048 * 3072, 192,
        ke, 192, (long long)16 * 2048 * 192, (long long)2048 * 192,
        attn, 2048, 16 * SS, SS,
        16, scaling);
    // 10. causal softmax (in place, zeros above diagonal)
    softmax_k<<<BATCH * NHEADS * S_LEN, 256>>>(attn);
    // 11. out[b, :, h*128:+128] = P @ vT^T  (KLIMIT; M=2048, N=128, K=2048)
    gemm_mma<false, true><<<dim3(1, 16, 32), 256>>>(
        2048, 128, 2048,
        attn, 2048, 16 * SS, SS,
        vT, 2048, (long long)16 * 128 * 2048, (long long)128 * 2048,
        obuf, 2048, (long long)2048 * 2048, 128,
        16, 1.f);
    // 13. attn_output = out @ wo^T      (4096 x 2048, K=2048)
    gemm_mma<false, false><<<dim3(16, 32, 1), 256>>>(
        4096, 2048, 2048, obuf, 2048, 0, 0, wo, 2048, 0, 0,
        outp, 2048, 0, 0, 1, 1.f);
}

// round 16
// speedup vs baseline: 2.3147x; 1.0510x over previous
#include <cuda_runtime.h>
#include <math.h>
#include <float.h>
#include <stdint.h>

// ---------------------------------------------------------------------------
// MLA prefill. B=2, S=2048, HIDDEN=2048, H=16, Q_LORA=768, KV_LORA=512,
// NOPE=128, ROPE=64, QK_HEAD=192, V_DIM=128.
// Outputs: attn_output (B,S,2048) then attn_weights (B,H,S,S), fp32.
// R15 structure (restructured algebra) + ldmatrix fragment loads:
//   A-frag: 1x ldmatrix.x4.b16 (was 4 scalar LDS), B-frag: 1x ldmatrix.x2.
// SMEM layout / staging / K-order identical to the passing R15 kernel.
// No cp.async / dynamic smem / tcgen05 (harness ptxas target rejects them).
// ---------------------------------------------------------------------------

#define S_LEN   2048
#define BATCH   2
#define NHEADS  16

// Scratch (device globals: no allocations allowed)
__device__ float g_qa[4096 * 768];
__device__ float g_q[(long long)4096 * 3072];       // q proj; pe cols roped in place
__device__ float g_kvfull[4096 * 576];
__device__ float g_kv_ext[4096 * 576];              // [rmsnorm(kv_lat) | rope(k_pe)]
__device__ float g_k_ext[(long long)32 * 2048 * 192]; // per (b,h): [k_nope | k_pe]
__device__ float g_vT[(long long)32 * 128 * 2048];    // per (b,h): V^T
__device__ float g_out[(long long)4096 * 2048];

__device__ __forceinline__ uint32_t f2tf(float x) {
    uint32_t r;
    asm("cvt.rna.tf32.f32 %0, %1;" : "=r"(r) : "f"(x));
    return r;
}

__device__ __forceinline__ void mma_tf32(float* c, const uint32_t* a,
                                         const uint32_t* b) {
    asm volatile(
        "mma.sync.aligned.m16n8k8.row.col.f32.tf32.tf32.f32 "
        "{%0,%1,%2,%3}, {%4,%5,%6,%7}, {%8,%9}, {%0,%1,%2,%3};"
        : "+f"(c[0]), "+f"(c[1]), "+f"(c[2]), "+f"(c[3])
        : "r"(a[0]), "r"(a[1]), "r"(a[2]), "r"(a[3]), "r"(b[0]), "r"(b[1]));
}

__device__ __forceinline__ void ldsm_x4(uint32_t* r, uint32_t saddr) {
    asm volatile(
        "ldmatrix.sync.aligned.m8n8.x4.shared.b16 {%0,%1,%2,%3}, [%4];"
        : "=r"(r[0]), "=r"(r[1]), "=r"(r[2]), "=r"(r[3]) : "r"(saddr));
}
__device__ __forceinline__ void ldsm_x2(uint32_t* r, uint32_t saddr) {
    asm volatile(
        "ldmatrix.sync.aligned.m8n8.x2.shared.b16 {%0,%1}, [%2];"
        : "=r"(r[0]), "=r"(r[1]) : "r"(saddr));
}

__device__ __forceinline__ uint32_t smem_u32(const void* p) {
    uint32_t a;
    asm("{ .reg .u64 t; cvta.to.shared.u64 t, %1; cvt.u32.u64 %0, t; }"
        : "=r"(a) : "l"(p));
    return a;
}

#define SM_STRIDE 20   // 16 + 4 padding (uint32 words); rows 16B-aligned

// ---------------------------------------------------------------------------
// Engine: C = alpha * A @ B^T.  CTA 128x128, warp 64x32, K-chunk 16,
// register-prefetch double buffer, one barrier per chunk, ldmatrix frags.
// CAUSAL: skip blocks fully above diagonal.  KLIMIT: k stops at m0+128.
// M % 128 == 0, K % 16 == 0; N boundary handled.
// ---------------------------------------------------------------------------
template<bool CAUSAL, bool KLIMIT>
__global__ __launch_bounds__(256, 2) void gemm_mma(
    int M, int N, int K,
    const float* __restrict__ A, int lda, long long sAo, long long sAi,
    const float* __restrict__ B, int ldb, long long sBo, long long sBi,
    float* __restrict__ C, int ldc, long long sCo, long long sCi,
    int zdiv, float alpha)
{
    const int m0 = blockIdx.y * 128;
    const int n0 = blockIdx.x * 128;
    if (CAUSAL && n0 > m0 + 127) return;

    __shared__ uint32_t As[2][128 * SM_STRIDE];
    __shared__ uint32_t Bs[2][128 * SM_STRIDE];

    const int z = blockIdx.z;
    const int zo = z / zdiv, zi = z % zdiv;
    A += zo * sAo + (long long)zi * sAi;
    B += zo * sBo + (long long)zi * sBi;
    C += zo * sCo + (long long)zi * sCi;

    const int kend = KLIMIT ? min(K, m0 + 128) : K;
    const int nkt = kend >> 4;

    const int tid  = threadIdx.x;
    const int lane = tid & 31;
    const int wid  = tid >> 5;
    const int wm   = wid & 1;
    const int wn   = wid >> 1;
    const int lr   = lane >> 2;
    const int lc   = lane & 3;

    const int row = tid >> 2;
    const int q   = tid & 3;

    // ldmatrix per-lane row-address offsets (in words), layout-invariant:
    //  A x4: mat0/1 = rows lr / lr+8 at col kk; mat2/3 = same rows at kk+4.
    //        lane supplies: row (lane&7) + 8*((lane>>3)&1), col +4 if lane>=16.
    //  B x2: lanes 0-15: row (lane&7), col +4 for lanes 8-15.
    const int aoffw = ((lane & 7) + (((lane >> 3) & 1) << 3)) * SM_STRIDE
                    + ((lane >> 4) << 2);
    const int boffw = (lane & 7) * SM_STRIDE + (((lane >> 3) & 1) << 2);

    const uint32_t asb[2] = { smem_u32(&As[0][0]), smem_u32(&As[1][0]) };
    const uint32_t bsb[2] = { smem_u32(&Bs[0][0]), smem_u32(&Bs[1][0]) };

    float4 ra[2], rb[2];
    auto gload = [&](int kt) {
        const int k0 = kt << 4;
#pragma unroll
        for (int i = 0; i < 2; i++) {
            const int r = i * 64 + row;
            ra[i] = *reinterpret_cast<const float4*>(
                &A[(long long)(m0 + r) * lda + k0 + q * 4]);
            const int n = n0 + r;
            rb[i] = (n < N)
                ? *reinterpret_cast<const float4*>(
                      &B[(long long)n * ldb + k0 + q * 4])
                : make_float4(0.f, 0.f, 0.f, 0.f);
        }
    };
    auto sstore = [&](int s) {
#pragma unroll
        for (int i = 0; i < 2; i++) {
            const int r = i * 64 + row;
            uint4 a = make_uint4(f2tf(ra[i].x), f2tf(ra[i].y),
                                 f2tf(ra[i].z), f2tf(ra[i].w));
            uint4 b = make_uint4(f2tf(rb[i].x), f2tf(rb[i].y),
                                 f2tf(rb[i].z), f2tf(rb[i].w));
            *reinterpret_cast<uint4*>(&As[s][r * SM_STRIDE + q * 4]) = a;
            *reinterpret_cast<uint4*>(&Bs[s][r * SM_STRIDE + q * 4]) = b;
        }
    };

    float acc[4][4][4];
#pragma unroll
    for (int i = 0; i < 4; i++)
#pragma unroll
        for (int j = 0; j < 4; j++)
#pragma unroll
            for (int r = 0; r < 4; r++) acc[i][j][r] = 0.f;

    gload(0);
    sstore(0);
    __syncthreads();

    for (int kt = 0; kt < nkt; kt++) {
        if (kt + 1 < nkt) gload(kt + 1);

        const int s = kt & 1;
        // per-lane base byte addresses for this buffer
        const uint32_t aBase = asb[s] + ((wm * 64) * SM_STRIDE + aoffw) * 4;
        const uint32_t bBase = bsb[s] + ((wn * 32) * SM_STRIDE + boffw) * 4;
#pragma unroll
        for (int kk = 0; kk < 16; kk += 8) {
            uint32_t bf[4][2];
#pragma unroll
            for (int nf = 0; nf < 4; nf++)
                ldsm_x2(bf[nf], bBase + (nf * 8 * SM_STRIDE + kk) * 4);
#pragma unroll
            for (int mf = 0; mf < 4; mf++) {
                uint32_t af[4];
                ldsm_x4(af, aBase + (mf * 16 * SM_STRIDE + kk) * 4);
#pragma unroll
                for (int nf = 0; nf < 4; nf++)
                    mma_tf32(acc[mf][nf], af, bf[nf]);
            }
        }
        if (kt + 1 < nkt) sstore((kt + 1) & 1);
        __syncthreads();
    }

#pragma unroll
    for (int mf = 0; mf < 4; mf++) {
        const int r = m0 + wm * 64 + mf * 16 + lr;
#pragma unroll
        for (int nf = 0; nf < 4; nf++) {
            const int cn = n0 + wn * 32 + nf * 8 + 2 * lc;
            if (cn < N) {
                float2 v0 = make_float2(alpha * acc[mf][nf][0],
                                        alpha * acc[mf][nf][1]);
                float2 v1 = make_float2(alpha * acc[mf][nf][2],
                                        alpha * acc[mf][nf][3]);
                *reinterpret_cast<float2*>(C + (long long)r * ldc + cn) = v0;
                *reinterpret_cast<float2*>(C + (long long)(r + 8) * ldc + cn) = v1;
            }
        }
    }
}

// ---------------------------------------------------------------------------
// RMSNorm
// ---------------------------------------------------------------------------
__global__ __launch_bounds__(256) void rmsnorm_k(
    const float* __restrict__ x, int ldx, const float* __restrict__ w,
    float* __restrict__ y, int ldy, int dim)
{
    const long long row = blockIdx.x;
    x += row * ldx; y += row * ldy;
    float s = 0.f;
    for (int i = threadIdx.x; i < dim; i += 256) { float v = x[i]; s += v * v; }
    __shared__ float red[8];
    for (int o = 16; o; o >>= 1) s += __shfl_xor_sync(0xffffffffu, s, o);
    if ((threadIdx.x & 31) == 0) red[threadIdx.x >> 5] = s;
    __syncthreads();
    if (threadIdx.x < 8) {
        float v = red[threadIdx.x];
        for (int o = 4; o; o >>= 1) v += __shfl_xor_sync(0xffu, v, o);
        if (threadIdx.x == 0) red[0] = v;
    }
    __syncthreads();
    const float r = rsqrtf(red[0] / (float)dim + 1e-6f);
    for (int i = threadIdx.x; i < dim; i += 256) y[i] = x[i] * r * w[i];
}

// ---------------------------------------------------------------------------
// In-place RoPE on q's pe columns (rotate_half form).
// ---------------------------------------------------------------------------
__global__ void rope_q_inplace(float* __restrict__ q,
                               const float* __restrict__ cosb,
                               const float* __restrict__ sinb)
{
    const int bs = blockIdx.x, h = blockIdx.y, i = threadIdx.x;  // i: 0..31
    float* x = q + (long long)bs * 3072 + h * 192 + 128;
    const float xi = x[i], xj = x[i + 32];
    const float c0 = cosb[(long long)bs * 64 + i];
    const float s0 = sinb[(long long)bs * 64 + i];
    const float c1 = cosb[(long long)bs * 64 + i + 32];
    const float s1 = sinb[(long long)bs * 64 + i + 32];
    x[i]      = xi * c0 - xj * s0;
    x[i + 32] = xj * c1 + xi * s1;
}

// RoPE k_pe into kv_ext[512:576]
__global__ void rope_k_k(const float* __restrict__ kvfull,
                         const float* __restrict__ cosb,
                         const float* __restrict__ sinb,
                         float* __restrict__ kv_ext)
{
    const int bs = blockIdx.x, i = threadIdx.x;
    const float* x = kvfull + (long long)bs * 576 + 512;
    const float c  = cosb[(long long)bs * 64 + i];
    const float sn = sinb[(long long)bs * 64 + i];
    const float xr = (i < 32) ? -x[i + 32] : x[i - 32];
    kv_ext[(long long)bs * 576 + 512 + i] = x[i] * c + xr * sn;
}

// Broadcast roped k_pe into k_ext[.., 128:192] for every head.
__global__ void kpe_bcast(const float* __restrict__ kv_ext,
                          float* __restrict__ k_ext)
{
    const int bs = blockIdx.x, h = blockIdx.y, i = threadIdx.x;  // i: 0..63
    const int b = bs >> 11, s = bs & 2047;
    k_ext[((long long)(b * 16 + h) * 2048 + s) * 192 + 128 + i] =
        kv_ext[(long long)bs * 576 + 512 + i];
}

// ---------------------------------------------------------------------------
// Causal in-place softmax
// ---------------------------------------------------------------------------
__global__ __launch_bounds__(256) void softmax_k(float* __restrict__ P)
{
    const long long row = blockIdx.x;
    const int s = (int)(row & (S_LEN - 1));
    float* p = P + row * S_LEN;
    const int tid = threadIdx.x;

    float v[8];
    float mx = -FLT_MAX;
#pragma unroll
    for (int i = 0; i < 8; i++) {
        const int t = tid + i * 256;
        v[i] = (t <= s) ? p[t] : -FLT_MAX;
        mx = fmaxf(mx, v[i]);
    }
    __shared__ float red[8];
    for (int o = 16; o; o >>= 1) mx = fmaxf(mx, __shfl_xor_sync(0xffffffffu, mx, o));
    if ((tid & 31) == 0) red[tid >> 5] = mx;
    __syncthreads();
    if (tid < 8) {
        float m2 = red[tid];
        for (int o = 4; o; o >>= 1) m2 = fmaxf(m2, __shfl_xor_sync(0xffu, m2, o));
        if (tid == 0) red[0] = m2;
    }
    __syncthreads();
    mx = red[0];
    __syncthreads();

    float sum = 0.f;
#pragma unroll
    for (int i = 0; i < 8; i++) {
        const int t = tid + i * 256;
        v[i] = (t <= s) ? __expf(v[i] - mx) : 0.f;
        sum += v[i];
    }
    for (int o = 16; o; o >>= 1) sum += __shfl_xor_sync(0xffffffffu, sum, o);
    if ((tid & 31) == 0) red[tid >> 5] = sum;
    __syncthreads();
    if (tid < 8) {
        float s2 = red[tid];
        for (int o = 4; o; o >>= 1) s2 += __shfl_xor_sync(0xffu, s2, o);
        if (tid == 0) red[0] = s2;
    }
    __syncthreads();
    const float inv = 1.f / red[0];
#pragma unroll
    for (int i = 0; i < 8; i++) p[tid + i * 256] = v[i] * inv;
}

// ---------------------------------------------------------------------------
extern "C" void kernel_launch(void* const* d_in, const int* in_sizes, int n_in,
                              void* d_out, int out_size)
{
    const float* hs    = (const float*)d_in[0];
    const float* cosb  = (const float*)d_in[1];
    const float* sinb  = (const float*)d_in[2];
    const float* wq_a  = (const float*)d_in[4];
    const float* qnw   = (const float*)d_in[5];
    const float* wq_b  = (const float*)d_in[6];
    const float* wkv_a = (const float*)d_in[7];
    const float* kvnw  = (const float*)d_in[8];
    const float* wkv_b = (const float*)d_in[9];
    const float* wo    = (const float*)d_in[10];

    float* outp = (float*)d_out;
    float* attn = outp + (long long)BATCH * S_LEN * 2048;

    float *qa, *q, *kvf, *kve, *ke, *vT, *obuf;
    cudaGetSymbolAddress((void**)&qa,   g_qa);
    cudaGetSymbolAddress((void**)&q,    g_q);
    cudaGetSymbolAddress((void**)&kvf,  g_kvfull);
    cudaGetSymbolAddress((void**)&kve,  g_kv_ext);
    cudaGetSymbolAddress((void**)&ke,   g_k_ext);
    cudaGetSymbolAddress((void**)&vT,   g_vT);
    cudaGetSymbolAddress((void**)&obuf, g_out);

    const float scaling = 1.f / sqrtf(192.f);
    const long long SS  = (long long)S_LEN * S_LEN;

    // 1. qa = hs @ wq_a^T               (4096 x 768, K=2048)
    gemm_mma<false, false><<<dim3(6, 32, 1), 256>>>(
        4096, 768, 2048, hs, 2048, 0, 0, wq_a, 2048, 0, 0,
        qa, 768, 0, 0, 1, 1.f);
    // 2. rmsnorm(qa)
    rmsnorm_k<<<4096, 256>>>(qa, 768, qnw, qa, 768, 768);
    // 3. q = qa @ wq_b^T                (4096 x 3072, K=768)
    gemm_mma<false, false><<<dim3(24, 32, 1), 256>>>(
        4096, 3072, 768, qa, 768, 0, 0, wq_b, 768, 0, 0,
        q, 3072, 0, 0, 1, 1.f);
    // 4. kvf = hs @ wkv_a^T             (4096 x 576, K=2048)
    gemm_mma<false, false><<<dim3(5, 32, 1), 256>>>(
        4096, 576, 2048, hs, 2048, 0, 0, wkv_a, 2048, 0, 0,
        kvf, 576, 0, 0, 1, 1.f);
    // 5-7. rmsnorm + rope (k into kve, q in place)
    rmsnorm_k<<<4096, 256>>>(kvf, 576, kvnw, kve, 576, 512);
    rope_k_k<<<4096, 64>>>(kvf, cosb, sinb, kve);
    rope_q_inplace<<<dim3(4096, 16), 32>>>(q, cosb, sinb);
    // 8a. k_ext[:, :128] = kv_lat @ Wb_nope_h^T  (per (b,h): 2048x128, K=512)
    gemm_mma<false, false><<<dim3(1, 16, 32), 256>>>(
        2048, 128, 512,
        kve, 576, (long long)2048 * 576, 0,
        wkv_b, 512, 0, (long long)256 * 512,
        ke, 192, (long long)16 * 2048 * 192, (long long)2048 * 192,
        16, 1.f);
    // 8b. k_ext[:, 128:192] = broadcast roped k_pe
    kpe_bcast<<<dim3(4096, 16), 64>>>(kve, ke);
    // 8c. vT[b,h] (128x2048) = Wb_v_h @ kv_lat^T  (M=128, N=2048, K=512)
    gemm_mma<false, false><<<dim3(16, 1, 32), 256>>>(
        128, 2048, 512,
        wkv_b + 128 * 512, 512, 0, (long long)256 * 512,
        kve, 576, (long long)2048 * 576, 0,
        vT, 2048, (long long)16 * 128 * 2048, (long long)128 * 2048,
        16, 1.f);
    // 9. scores = scaling * q[:, h*192:+192] @ k_ext^T (causal, K=192)
    gemm_mma<true, false><<<dim3(16, 16, 32), 256>>>(
        2048, 2048, 192,
        q, 3072, (long long)2048 * 3072, 192,
        ke, 192, (long long)16 * 2048 * 192, (long long)2048 * 192,
        attn, 2048, 16 * SS, SS,
        16, scaling);
    // 10. causal softmax (in place, zeros above diagonal)
    softmax_k<<<BATCH * NHEADS * S_LEN, 256>>>(attn);
    // 11. out[b, :, h*128:+128] = P @ vT^T  (KLIMIT; M=2048, N=128, K=2048)
    gemm_mma<false, true><<<dim3(1, 16, 32), 256>>>(
        2048, 128, 2048,
        attn, 2048, 16 * SS, SS,
        vT, 2048, (long long)16 * 128 * 2048, (long long)128 * 2048,
        obuf, 2048, (long long)2048 * 2048, 128,
        16, 1.f);
    // 13. attn_output = out @ wo^T      (4096 x 2048, K=2048)
    gemm_mma<false, false><<<dim3(16, 32, 1), 256>>>(
        4096, 2048, 2048, obuf, 2048, 0, 0, wo, 2048, 0, 0,
        outp, 2048, 0, 0, 1, 1.f);
}

// round 17
// speedup vs baseline: 2.4275x; 1.0488x over previous
#include <cuda_runtime.h>
#include <math.h>
#include <float.h>
#include <stdint.h>

// ---------------------------------------------------------------------------
// MLA prefill. B=2, S=2048, HIDDEN=2048, H=16, Q_LORA=768, KV_LORA=512,
// NOPE=128, ROPE=64, QK_HEAD=192, V_DIM=128.
// Outputs: attn_output (B,S,2048) then attn_weights (B,H,S,S), fp32.
// R16 + pre-rounded tf32 operands (no cvt in GEMM mainloop) + B via ldsm.x4.
// No cp.async / dynamic smem / tcgen05 (harness ptxas target rejects them).
// ---------------------------------------------------------------------------

#define S_LEN   2048
#define BATCH   2
#define NHEADS  16

// Scratch (device globals: no allocations allowed)
__device__ float g_qa[4096 * 768];
__device__ float g_q[(long long)4096 * 3072];
__device__ float g_kvfull[4096 * 576];
__device__ float g_kv_ext[4096 * 576];
__device__ float g_k_ext[(long long)32 * 2048 * 192];
__device__ float g_vT[(long long)32 * 128 * 2048];
__device__ float g_out[(long long)4096 * 2048];
// tf32-rounded copies of inputs
__device__ float g_hsT[4096 * 2048];
__device__ float g_wqaT[768 * 2048];
__device__ float g_wqbT[3072 * 768];
__device__ float g_wkvaT[576 * 2048];
__device__ float g_wkvbT[4096 * 512];
__device__ float g_woT[2048 * 2048];

__device__ __forceinline__ uint32_t f2tf(float x) {
    uint32_t r;
    asm("cvt.rna.tf32.f32 %0, %1;" : "=r"(r) : "f"(x));
    return r;
}
__device__ __forceinline__ float f2tff(float x) {
    return __uint_as_float(f2tf(x));
}

__device__ __forceinline__ void mma_tf32(float* c, const uint32_t* a,
                                         const uint32_t* b) {
    asm volatile(
        "mma.sync.aligned.m16n8k8.row.col.f32.tf32.tf32.f32 "
        "{%0,%1,%2,%3}, {%4,%5,%6,%7}, {%8,%9}, {%0,%1,%2,%3};"
        : "+f"(c[0]), "+f"(c[1]), "+f"(c[2]), "+f"(c[3])
        : "r"(a[0]), "r"(a[1]), "r"(a[2]), "r"(a[3]), "r"(b[0]), "r"(b[1]));
}

__device__ __forceinline__ void ldsm_x4(uint32_t* r, uint32_t saddr) {
    asm volatile(
        "ldmatrix.sync.aligned.m8n8.x4.shared.b16 {%0,%1,%2,%3}, [%4];"
        : "=r"(r[0]), "=r"(r[1]), "=r"(r[2]), "=r"(r[3]) : "r"(saddr));
}

__device__ __forceinline__ uint32_t smem_u32(const void* p) {
    uint32_t a;
    asm("{ .reg .u64 t; cvta.to.shared.u64 t, %1; cvt.u32.u64 %0, t; }"
        : "=r"(a) : "l"(p));
    return a;
}

#define SM_STRIDE 20   // 16 + 4 padding (uint32 words); rows 16B-aligned

// ---------------------------------------------------------------------------
// Engine: C = alpha * A @ B^T.  CTA 128x128, warp 64x32, K-chunk 16,
// register-prefetch double buffer, one barrier per chunk, ldmatrix frags.
// Inputs MUST be tf32-pre-rounded (staging is a raw copy).
// roundC: round C to tf32 on store (for tensors feeding later GEMMs).
// CAUSAL: skip blocks fully above diagonal.  KLIMIT: k stops at m0+128.
// ---------------------------------------------------------------------------
template<bool CAUSAL, bool KLIMIT>
__global__ __launch_bounds__(256, 2) void gemm_mma(
    int M, int N, int K,
    const float* __restrict__ A, int lda, long long sAo, long long sAi,
    const float* __restrict__ B, int ldb, long long sBo, long long sBi,
    float* __restrict__ C, int ldc, long long sCo, long long sCi,
    int zdiv, float alpha, int roundC)
{
    const int m0 = blockIdx.y * 128;
    const int n0 = blockIdx.x * 128;
    if (CAUSAL && n0 > m0 + 127) return;

    __shared__ uint32_t As[2][128 * SM_STRIDE];
    __shared__ uint32_t Bs[2][128 * SM_STRIDE];

    const int z = blockIdx.z;
    const int zo = z / zdiv, zi = z % zdiv;
    A += zo * sAo + (long long)zi * sAi;
    B += zo * sBo + (long long)zi * sBi;
    C += zo * sCo + (long long)zi * sCi;

    const int kend = KLIMIT ? min(K, m0 + 128) : K;
    const int nkt = kend >> 4;

    const int tid  = threadIdx.x;
    const int lane = tid & 31;
    const int wid  = tid >> 5;
    const int wm   = wid & 1;
    const int wn   = wid >> 1;
    const int lr   = lane >> 2;
    const int lc   = lane & 3;

    const int row = tid >> 2;
    const int q   = tid & 3;

    // ldmatrix lane-address offsets (words):
    //  A x4: mat0=rows lr col kk, mat1=rows lr+8, mat2=rows lr col kk+4, mat3=+8/+4
    const int aoffw = ((lane & 7) + (((lane >> 3) & 1) << 3)) * SM_STRIDE
                    + ((lane >> 4) << 2);
    //  B x4 (two n-frags): mat0=rows nf8 col kk, mat1=rows nf8 col kk+4,
    //                      mat2=rows (nf+1)8 col kk, mat3=rows (nf+1)8 col kk+4
    const int boffw = ((lane & 7) + (((lane >> 4) & 1) << 3)) * SM_STRIDE
                    + (((lane >> 3) & 1) << 2);

    const uint32_t asb[2] = { smem_u32(&As[0][0]), smem_u32(&As[1][0]) };
    const uint32_t bsb[2] = { smem_u32(&Bs[0][0]), smem_u32(&Bs[1][0]) };

    float4 ra[2], rb[2];
    auto gload = [&](int kt) {
        const int k0 = kt << 4;
#pragma unroll
        for (int i = 0; i < 2; i++) {
            const int r = i * 64 + row;
            ra[i] = *reinterpret_cast<const float4*>(
                &A[(long long)(m0 + r) * lda + k0 + q * 4]);
            const int n = n0 + r;
            rb[i] = (n < N)
                ? *reinterpret_cast<const float4*>(
                      &B[(long long)n * ldb + k0 + q * 4])
                : make_float4(0.f, 0.f, 0.f, 0.f);
        }
    };
    auto sstore = [&](int s) {      // raw copy — inputs already tf32
#pragma unroll
        for (int i = 0; i < 2; i++) {
            const int r = i * 64 + row;
            *reinterpret_cast<float4*>(&As[s][r * SM_STRIDE + q * 4]) = ra[i];
            *reinterpret_cast<float4*>(&Bs[s][r * SM_STRIDE + q * 4]) = rb[i];
        }
    };

    float acc[4][4][4];
#pragma unroll
    for (int i = 0; i < 4; i++)
#pragma unroll
        for (int j = 0; j < 4; j++)
#pragma unroll
            for (int r = 0; r < 4; r++) acc[i][j][r] = 0.f;

    gload(0);
    sstore(0);
    __syncthreads();

    for (int kt = 0; kt < nkt; kt++) {
        if (kt + 1 < nkt) gload(kt + 1);

        const int s = kt & 1;
        const uint32_t aBase = asb[s] + ((wm * 64) * SM_STRIDE + aoffw) * 4;
        const uint32_t bBase = bsb[s] + ((wn * 32) * SM_STRIDE + boffw) * 4;
#pragma unroll
        for (int kk = 0; kk < 16; kk += 8) {
            uint32_t bf[4][2];
#pragma unroll
            for (int nf = 0; nf < 4; nf += 2)
                ldsm_x4(&bf[nf][0], bBase + (nf * 8 * SM_STRIDE + kk) * 4);
#pragma unroll
            for (int mf = 0; mf < 4; mf++) {
                uint32_t af[4];
                ldsm_x4(af, aBase + (mf * 16 * SM_STRIDE + kk) * 4);
#pragma unroll
                for (int nf = 0; nf < 4; nf++)
                    mma_tf32(acc[mf][nf], af, bf[nf]);
            }
        }
        if (kt + 1 < nkt) sstore((kt + 1) & 1);
        __syncthreads();
    }

#pragma unroll
    for (int mf = 0; mf < 4; mf++) {
        const int r = m0 + wm * 64 + mf * 16 + lr;
#pragma unroll
        for (int nf = 0; nf < 4; nf++) {
            const int cn = n0 + wn * 32 + nf * 8 + 2 * lc;
            if (cn < N) {
                float o0 = alpha * acc[mf][nf][0];
                float o1 = alpha * acc[mf][nf][1];
                float o2 = alpha * acc[mf][nf][2];
                float o3 = alpha * acc[mf][nf][3];
                if (roundC) {
                    o0 = f2tff(o0); o1 = f2tff(o1);
                    o2 = f2tff(o2); o3 = f2tff(o3);
                }
                *reinterpret_cast<float2*>(C + (long long)r * ldc + cn) =
                    make_float2(o0, o1);
                *reinterpret_cast<float2*>(C + (long long)(r + 8) * ldc + cn) =
                    make_float2(o2, o3);
            }
        }
    }
}

// ---------------------------------------------------------------------------
// Elementwise tf32 rounding pass (float4, grid-stride)
// ---------------------------------------------------------------------------
__global__ void round_tf32_k(const float* __restrict__ in,
                             float* __restrict__ out, long long n4)
{
    for (long long i = blockIdx.x * 256ll + threadIdx.x; i < n4;
         i += (long long)gridDim.x * 256) {
        float4 v = reinterpret_cast<const float4*>(in)[i];
        v.x = f2tff(v.x); v.y = f2tff(v.y);
        v.z = f2tff(v.z); v.w = f2tff(v.w);
        reinterpret_cast<float4*>(out)[i] = v;
    }
}

// ---------------------------------------------------------------------------
// RMSNorm (tf32-rounded output)
// ---------------------------------------------------------------------------
__global__ __launch_bounds__(256) void rmsnorm_k(
    const float* __restrict__ x, int ldx, const float* __restrict__ w,
    float* __restrict__ y, int ldy, int dim)
{
    const long long row = blockIdx.x;
    x += row * ldx; y += row * ldy;
    float s = 0.f;
    for (int i = threadIdx.x; i < dim; i += 256) { float v = x[i]; s += v * v; }
    __shared__ float red[8];
    for (int o = 16; o; o >>= 1) s += __shfl_xor_sync(0xffffffffu, s, o);
    if ((threadIdx.x & 31) == 0) red[threadIdx.x >> 5] = s;
    __syncthreads();
    if (threadIdx.x < 8) {
        float v = red[threadIdx.x];
        for (int o = 4; o; o >>= 1) v += __shfl_xor_sync(0xffu, v, o);
        if (threadIdx.x == 0) red[0] = v;
    }
    __syncthreads();
    const float r = rsqrtf(red[0] / (float)dim + 1e-6f);
    for (int i = threadIdx.x; i < dim; i += 256)
        y[i] = f2tff(x[i] * r * w[i]);
}

// ---------------------------------------------------------------------------
// In-place RoPE on q's pe columns (rotate_half form), tf32-rounded.
// ---------------------------------------------------------------------------
__global__ void rope_q_inplace(float* __restrict__ q,
                               const float* __restrict__ cosb,
                               const float* __restrict__ sinb)
{
    const int bs = blockIdx.x, h = blockIdx.y, i = threadIdx.x;  // i: 0..31
    float* x = q + (long long)bs * 3072 + h * 192 + 128;
    const float xi = x[i], xj = x[i + 32];
    const float c0 = cosb[(long long)bs * 64 + i];
    const float s0 = sinb[(long long)bs * 64 + i];
    const float c1 = cosb[(long long)bs * 64 + i + 32];
    const float s1 = sinb[(long long)bs * 64 + i + 32];
    x[i]      = f2tff(xi * c0 - xj * s0);
    x[i + 32] = f2tff(xj * c1 + xi * s1);
}

// RoPE k_pe into kv_ext[512:576], tf32-rounded
__global__ void rope_k_k(const float* __restrict__ kvfull,
                         const float* __restrict__ cosb,
                         const float* __restrict__ sinb,
                         float* __restrict__ kv_ext)
{
    const int bs = blockIdx.x, i = threadIdx.x;
    const float* x = kvfull + (long long)bs * 576 + 512;
    const float c  = cosb[(long long)bs * 64 + i];
    const float sn = sinb[(long long)bs * 64 + i];
    const float xr = (i < 32) ? -x[i + 32] : x[i - 32];
    kv_ext[(long long)bs * 576 + 512 + i] = f2tff(x[i] * c + xr * sn);
}

// Broadcast roped (already-rounded) k_pe into k_ext[.., 128:192].
__global__ void kpe_bcast(const float* __restrict__ kv_ext,
                          float* __restrict__ k_ext)
{
    const int bs = blockIdx.x, h = blockIdx.y, i = threadIdx.x;  // i: 0..63
    const int b = bs >> 11, s = bs & 2047;
    k_ext[((long long)(b * 16 + h) * 2048 + s) * 192 + 128 + i] =
        kv_ext[(long long)bs * 576 + 512 + i];
}

// ---------------------------------------------------------------------------
// Causal in-place softmax; writes tf32-rounded probabilities.
// ---------------------------------------------------------------------------
__global__ __launch_bounds__(256) void softmax_k(float* __restrict__ P)
{
    const long long row = blockIdx.x;
    const int s = (int)(row & (S_LEN - 1));
    float* p = P + row * S_LEN;
    const int tid = threadIdx.x;

    float v[8];
    float mx = -FLT_MAX;
#pragma unroll
    for (int i = 0; i < 8; i++) {
        const int t = tid + i * 256;
        v[i] = (t <= s) ? p[t] : -FLT_MAX;
        mx = fmaxf(mx, v[i]);
    }
    __shared__ float red[8];
    for (int o = 16; o; o >>= 1) mx = fmaxf(mx, __shfl_xor_sync(0xffffffffu, mx, o));
    if ((tid & 31) == 0) red[tid >> 5] = mx;
    __syncthreads();
    if (tid < 8) {
        float m2 = red[tid];
        for (int o = 4; o; o >>= 1) m2 = fmaxf(m2, __shfl_xor_sync(0xffu, m2, o));
        if (tid == 0) red[0] = m2;
    }
    __syncthreads();
    mx = red[0];
    __syncthreads();

    float sum = 0.f;
#pragma unroll
    for (int i = 0; i < 8; i++) {
        const int t = tid + i * 256;
        v[i] = (t <= s) ? __expf(v[i] - mx) : 0.f;
        sum += v[i];
    }
    for (int o = 16; o; o >>= 1) sum += __shfl_xor_sync(0xffffffffu, sum, o);
    if ((tid & 31) == 0) red[tid >> 5] = sum;
    __syncthreads();
    if (tid < 8) {
        float s2 = red[tid];
        for (int o = 4; o; o >>= 1) s2 += __shfl_xor_sync(0xffu, s2, o);
        if (tid == 0) red[0] = s2;
    }
    __syncthreads();
    const float inv = 1.f / red[0];
#pragma unroll
    for (int i = 0; i < 8; i++) p[tid + i * 256] = f2tff(v[i] * inv);
}

// ---------------------------------------------------------------------------
extern "C" void kernel_launch(void* const* d_in, const int* in_sizes, int n_in,
                              void* d_out, int out_size)
{
    const float* hs    = (const float*)d_in[0];
    const float* cosb  = (const float*)d_in[1];
    const float* sinb  = (const float*)d_in[2];
    const float* wq_a  = (const float*)d_in[4];
    const float* qnw   = (const float*)d_in[5];
    const float* wq_b  = (const float*)d_in[6];
    const float* wkv_a = (const float*)d_in[7];
    const float* kvnw  = (const float*)d_in[8];
    const float* wkv_b = (const float*)d_in[9];
    const float* wo    = (const float*)d_in[10];

    float* outp = (float*)d_out;
    float* attn = outp + (long long)BATCH * S_LEN * 2048;

    float *qa, *q, *kvf, *kve, *ke, *vT, *obuf;
    float *hsT, *wqaT, *wqbT, *wkvaT, *wkvbT, *woT;
    cudaGetSymbolAddress((void**)&qa,    g_qa);
    cudaGetSymbolAddress((void**)&q,     g_q);
    cudaGetSymbolAddress((void**)&kvf,   g_kvfull);
    cudaGetSymbolAddress((void**)&kve,   g_kv_ext);
    cudaGetSymbolAddress((void**)&ke,    g_k_ext);
    cudaGetSymbolAddress((void**)&vT,    g_vT);
    cudaGetSymbolAddress((void**)&obuf,  g_out);
    cudaGetSymbolAddress((void**)&hsT,   g_hsT);
    cudaGetSymbolAddress((void**)&wqaT,  g_wqaT);
    cudaGetSymbolAddress((void**)&wqbT,  g_wqbT);
    cudaGetSymbolAddress((void**)&wkvaT, g_wkvaT);
    cudaGetSymbolAddress((void**)&wkvbT, g_wkvbT);
    cudaGetSymbolAddress((void**)&woT,   g_woT);

    const float scaling = 1.f / sqrtf(192.f);
    const long long SS  = (long long)S_LEN * S_LEN;

    // 0. tf32-round inputs once
    round_tf32_k<<<592, 256>>>(hs,    hsT,   (long long)4096 * 2048 / 4);
    round_tf32_k<<<592, 256>>>(wq_a,  wqaT,  (long long)768 * 2048 / 4);
    round_tf32_k<<<592, 256>>>(wq_b,  wqbT,  (long long)3072 * 768 / 4);
    round_tf32_k<<<592, 256>>>(wkv_a, wkvaT, (long long)576 * 2048 / 4);
    round_tf32_k<<<592, 256>>>(wkv_b, wkvbT, (long long)4096 * 512 / 4);
    round_tf32_k<<<592, 256>>>(wo,    woT,   (long long)2048 * 2048 / 4);

    // 1. qa = hsT @ wqaT^T              (4096 x 768, K=2048); rmsnorm rounds
    gemm_mma<false, false><<<dim3(6, 32, 1), 256>>>(
        4096, 768, 2048, hsT, 2048, 0, 0, wqaT, 2048, 0, 0,
        qa, 768, 0, 0, 1, 1.f, 0);
    // 2. rmsnorm(qa) -> rounded
    rmsnorm_k<<<4096, 256>>>(qa, 768, qnw, qa, 768, 768);
    // 3. q = qa @ wqbT^T                (4096 x 3072, K=768) -> rounded
    gemm_mma<false, false><<<dim3(24, 32, 1), 256>>>(
        4096, 3072, 768, qa, 768, 0, 0, wqbT, 768, 0, 0,
        q, 3072, 0, 0, 1, 1.f, 1);
    // 4. kvf = hsT @ wkvaT^T            (4096 x 576, K=2048); consumers round
    gemm_mma<false, false><<<dim3(5, 32, 1), 256>>>(
        4096, 576, 2048, hsT, 2048, 0, 0, wkvaT, 2048, 0, 0,
        kvf, 576, 0, 0, 1, 1.f, 0);
    // 5-7. rmsnorm + rope (rounded writes)
    rmsnorm_k<<<4096, 256>>>(kvf, 576, kvnw, kve, 576, 512);
    rope_k_k<<<4096, 64>>>(kvf, cosb, sinb, kve);
    rope_q_inplace<<<dim3(4096, 16), 32>>>(q, cosb, sinb);
    // 8a. k_ext[:, :128] = kve @ Wb_nope_h^T -> rounded
    gemm_mma<false, false><<<dim3(1, 16, 32), 256>>>(
        2048, 128, 512,
        kve, 576, (long long)2048 * 576, 0,
        wkvbT, 512, 0, (long long)256 * 512,
        ke, 192, (long long)16 * 2048 * 192, (long long)2048 * 192,
        16, 1.f, 1);
    // 8b. k_ext[:, 128:192] = broadcast rounded k_pe
    kpe_bcast<<<dim3(4096, 16), 64>>>(kve, ke);
    // 8c. vT[b,h] = Wb_v_h @ kve^T -> rounded  (M=128, N=2048, K=512)
    gemm_mma<false, false><<<dim3(16, 1, 32), 256>>>(
        128, 2048, 512,
        wkvbT + 128 * 512, 512, 0, (long long)256 * 512,
        kve, 576, (long long)2048 * 576, 0,
        vT, 2048, (long long)16 * 128 * 2048, (long long)128 * 2048,
        16, 1.f, 1);
    // 9. scores = scaling * q_h @ k_ext^T (causal, K=192) — NOT rounded (output)
    gemm_mma<true, false><<<dim3(16, 16, 32), 256>>>(
        2048, 2048, 192,
        q, 3072, (long long)2048 * 3072, 192,
        ke, 192, (long long)16 * 2048 * 192, (long long)2048 * 192,
        attn, 2048, 16 * SS, SS,
        16, scaling, 0);
    // 10. causal softmax (in place); writes tf32-rounded P
    softmax_k<<<BATCH * NHEADS * S_LEN, 256>>>(attn);
    // 11. out[b, :, h*128:+128] = P @ vT^T (KLIMIT) -> rounded
    gemm_mma<false, true><<<dim3(1, 16, 32), 256>>>(
        2048, 128, 2048,
        attn, 2048, 16 * SS, SS,
        vT, 2048, (long long)16 * 128 * 2048, (long long)128 * 2048,
        obuf, 2048, (long long)2048 * 2048, 128,
        16, 1.f, 1);
    // 13. attn_output = obuf @ woT^T    (4096 x 2048, K=2048) — final, unrounded
    gemm_mma<false, false><<<dim3(16, 32, 1), 256>>>(
        4096, 2048, 2048, obuf, 2048, 0, 0, woT, 2048, 0, 0,
        outp, 2048, 0, 0, 1, 1.f, 0);
}